// round 14
// baseline (speedup 1.0000x reference)
#include <cuda_runtime.h>
#include <cuda_bf16.h>
#include <cuda_fp16.h>
#include <cstdint>

#define NNODES 100000
#define DEG 16
#define DIM 128
#define NC 256
#define MROWS 64    // CTA row tile

// ---------------- scratch (no allocation allowed) ----------------
__device__ __half g_zh[(size_t)NNODES * DIM];                // z in fp16 (gather source)
__device__ __half g_zih[(size_t)NNODES * DIM];               // z_i in fp16
__device__ __nv_bfloat16 g_Ah[(size_t)NNODES * DIM];         // layer-2 GEMM input hi
__device__ __nv_bfloat16 g_Al[(size_t)NNODES * DIM];         // layer-2 GEMM input lo
__device__ __nv_bfloat16 g_Bh[2 * NC * DIM];                 // both layers' weights hi [256 x 128] K-contig
__device__ __nv_bfloat16 g_Bl[2 * NC * DIM];                 // both layers' weights lo
__device__ float g_ssrc[NNODES];
__device__ float g_sdst[NNODES];

__device__ __forceinline__ uint32_t smem_u32(const void* p) {
    uint32_t a;
    asm("{ .reg .u64 t; cvta.to.shared.u64 t, %1; cvt.u32.u64 %0, t; }" : "=r"(a) : "l"(p));
    return a;
}

__device__ __forceinline__ void split_bf16(float x, __nv_bfloat16& h, __nv_bfloat16& l) {
    h = __float2bfloat16(x);
    l = __float2bfloat16(x - __bfloat162float(h));
}

// cp.async 16B with zero-fill when srcbytes==0
__device__ __forceinline__ void cp_async16(uint32_t dst, const void* src, int srcbytes) {
    asm volatile("cp.async.ca.shared.global [%0], [%1], 16, %2;"
                 :: "r"(dst), "l"(src), "r"(srcbytes) : "memory");
}
__device__ __forceinline__ void cp_async_commit() {
    asm volatile("cp.async.commit_group;" ::: "memory");
}

// ---------------- weight prep (both layers, one launch) ----------------
__global__ void prep_w_kernel(const float* __restrict__ W_W1, const float* __restrict__ W_U1,
                              const float* __restrict__ W_W2, const float* __restrict__ W_U2) {
    int idx = blockIdx.x * blockDim.x + threadIdx.x;
    if (idx >= 2 * NC * DIM) return;
    int layer = idx / (NC * DIM);
    int li = idx - layer * (NC * DIM);
    const float* WW = layer ? W_W2 : W_W1;
    const float* WU = layer ? W_U2 : W_U1;
    float v = (li < DIM * DIM) ? WW[li] : WU[li - DIM * DIM];
    __nv_bfloat16 h, l;
    split_bf16(v, h, l);
    g_Bh[idx] = h;
    g_Bl[idx] = l;
}

// ---------------- mma.sync GEMM, B software-pipelined over four 64-col chunks ----------------
// CTA = 64 rows, 256 threads, 8 warps 4M x 2N -> 16x32 warp tiles per chunk.
// B chunk nb+1 prefetched via cp.async while chunk nb computes. 2 CTAs/SM.
#define TPITCH 272
#define A_TILE_SM (MROWS * TPITCH)      // 17408 B
#define B_TILE_SM (MROWS * TPITCH)      // 17408 B per bf16 tile (64 N-rows)
#define B_BUF_SM  (2 * B_TILE_SM)       // hi + lo = 34816 B
#define CPITCH 68                       // fp32 staging pitch (floats), 64x68x4 = 17408 B
#define SMEM_DYN (2 * A_TILE_SM + 2 * B_BUF_SM)   // 104448 B -> 2 CTAs/SM

__device__ __forceinline__ void load_tile_cpasync(uint32_t sm_dst, const __nv_bfloat16* __restrict__ gptr,
                                                  int rowBase, int maxRows, int tid) {
#pragma unroll
    for (int it = 0; it < 4; it++) {
        int chunk = tid + it * 256;       // 1024 chunks of 16B (64 rows x 16)
        int row = chunk >> 4;
        int c8  = chunk & 15;
        int grow = rowBase + row;
        cp_async16(sm_dst + row * TPITCH + c8 * 16,
                   gptr + (size_t)grow * DIM + c8 * 8,
                   (grow < maxRows) ? 16 : 0);
    }
}

// fp32 source: split hi/lo while loading (layer-1 A = attr)
__device__ __forceinline__ void load_tile_fp32split(uint32_t sm_hi, uint32_t sm_lo,
                                                    const float* __restrict__ gptr,
                                                    int rowBase, int maxRows, int tid) {
#pragma unroll
    for (int it = 0; it < 4; it++) {
        int chunk = tid + it * 256;       // 1024 chunks (64 rows)
        int row = chunk >> 4;
        int c8  = chunk & 15;
        float f[8] = {0.f, 0.f, 0.f, 0.f, 0.f, 0.f, 0.f, 0.f};
        int grow = rowBase + row;
        if (grow < maxRows) {
            const float4* p = reinterpret_cast<const float4*>(gptr + (size_t)grow * DIM + c8 * 8);
            float4 v0 = p[0], v1 = p[1];
            f[0] = v0.x; f[1] = v0.y; f[2] = v0.z; f[3] = v0.w;
            f[4] = v1.x; f[5] = v1.y; f[6] = v1.z; f[7] = v1.w;
        }
        __nv_bfloat16 hh[8], ll[8];
#pragma unroll
        for (int j = 0; j < 8; j++) split_bf16(f[j], hh[j], ll[j]);
        uint4 vh = *reinterpret_cast<uint4*>(hh);
        uint4 vl = *reinterpret_cast<uint4*>(ll);
        uint32_t off = (uint32_t)(row * TPITCH + c8 * 16);
        asm volatile("st.shared.v4.b32 [%0], {%1,%2,%3,%4};"
                     :: "r"(sm_hi + off), "r"(vh.x), "r"(vh.y), "r"(vh.z), "r"(vh.w) : "memory");
        asm volatile("st.shared.v4.b32 [%0], {%1,%2,%3,%4};"
                     :: "r"(sm_lo + off), "r"(vl.x), "r"(vl.y), "r"(vl.z), "r"(vl.w) : "memory");
    }
}

__device__ __forceinline__ void ldsm_x4(uint32_t* r, uint32_t addr) {
    asm volatile("ldmatrix.sync.aligned.m8n8.x4.shared.b16 {%0,%1,%2,%3}, [%4];"
                 : "=r"(r[0]), "=r"(r[1]), "=r"(r[2]), "=r"(r[3]) : "r"(addr));
}
__device__ __forceinline__ void mma_bf16(float* d, const uint32_t* a, const uint32_t* b) {
    asm volatile("mma.sync.aligned.m16n8k16.row.col.f32.bf16.bf16.f32 "
                 "{%0,%1,%2,%3}, {%4,%5,%6,%7}, {%8,%9}, {%0,%1,%2,%3};"
                 : "+f"(d[0]), "+f"(d[1]), "+f"(d[2]), "+f"(d[3])
                 : "r"(a[0]), "r"(a[1]), "r"(a[2]), "r"(a[3]), "r"(b[0]), "r"(b[1]));
}

__global__ __launch_bounds__(256, 2)
void mma_gemm_kernel(const float* __restrict__ attr, const float* __restrict__ Wa,
                     int M, int srcFp32, int layer) {
    extern __shared__ char dynsmem[];
    uint32_t s0 = smem_u32(dynsmem);
    const uint32_t SM_AH = s0;
    const uint32_t SM_AL = s0 + A_TILE_SM;
    const uint32_t SM_B0 = s0 + 2 * A_TILE_SM;              // buffer 0: BH, BL
    const uint32_t SM_B1 = s0 + 2 * A_TILE_SM + B_BUF_SM;   // buffer 1: BH, BL

    int tid  = threadIdx.x;
    int wid  = tid >> 5;
    int lane = tid & 31;
    int warpM = (wid & 3) * 16;                // 4 warps along M (16 rows)
    int warpN = (wid >> 2) * 32;               // 2 warps along N (32 cols of the 64-col chunk)
    int rowBase = blockIdx.x * MROWS;

    const __nv_bfloat16* BhL = g_Bh + (size_t)layer * NC * DIM;
    const __nv_bfloat16* BlL = g_Bl + (size_t)layer * NC * DIM;

    // ---- prologue: A + B chunk 0 ----
    if (srcFp32)
        load_tile_fp32split(SM_AH, SM_AL, attr, rowBase, M, tid);
    else {
        load_tile_cpasync(SM_AH, g_Ah, rowBase, M, tid);
        load_tile_cpasync(SM_AL, g_Al, rowBase, M, tid);
    }
    load_tile_cpasync(SM_B0,             BhL, 0, 1 << 30, tid);
    load_tile_cpasync(SM_B0 + B_TILE_SM, BlL, 0, 1 << 30, tid);
    cp_async_commit();                      // group 0: A (if async) + B chunk 0

    int aRow = (lane & 15);
    int aK   = (lane >> 4) << 3;
    int bRow = (lane & 7) + ((lane >> 4) << 3);
    int bK   = ((lane >> 3) & 1) << 3;

    uint32_t aBase  = (warpM + aRow) * TPITCH + aK * 2;
    uint32_t bOff0  = (warpN +  0 + bRow) * TPITCH + bK * 2;
    uint32_t bOff1  = (warpN + 16 + bRow) * TPITCH + bK * 2;

    int half = lane >> 4;                  // 0/1: which of the 2 rows this half-warp handles
    int l16  = lane & 15;
    float pss[4] = {0.f, 0.f, 0.f, 0.f};
    float psd[4] = {0.f, 0.f, 0.f, 0.f};

#pragma unroll
    for (int nb = 0; nb < 4; nb++) {
        // prefetch next chunk into the other buffer (overlaps this chunk's compute)
        if (nb < 3) {
            uint32_t bufP = ((nb + 1) & 1) ? SM_B1 : SM_B0;
            load_tile_cpasync(bufP,             BhL + (size_t)(nb + 1) * 64 * DIM, 0, 1 << 30, tid);
            load_tile_cpasync(bufP + B_TILE_SM, BlL + (size_t)(nb + 1) * 64 * DIM, 0, 1 << 30, tid);
            cp_async_commit();
        }
        if (nb < 3) asm volatile("cp.async.wait_group 1;" ::: "memory");
        else        asm volatile("cp.async.wait_group 0;" ::: "memory");
        __syncthreads();

        uint32_t bufC = (nb & 1) ? SM_B1 : SM_B0;
        uint32_t BH = bufC, BL = bufC + B_TILE_SM;

        float acc[4][4];
#pragma unroll
        for (int ni = 0; ni < 4; ni++)
#pragma unroll
            for (int j = 0; j < 4; j++) acc[ni][j] = 0.f;

#pragma unroll
        for (int ks = 0; ks < 8; ks++) {
            uint32_t kb = (uint32_t)ks * 32u;  // 16 cols * 2B
            uint32_t ah[4], al[4];
            ldsm_x4(ah, SM_AH + aBase + kb);
            ldsm_x4(al, SM_AL + aBase + kb);
            uint32_t bh[4][2], bl[4][2];
            {
                uint32_t r[4];
                ldsm_x4(r, BH + bOff0 + kb);
                bh[0][0] = r[0]; bh[0][1] = r[1]; bh[1][0] = r[2]; bh[1][1] = r[3];
                ldsm_x4(r, BH + bOff1 + kb);
                bh[2][0] = r[0]; bh[2][1] = r[1]; bh[3][0] = r[2]; bh[3][1] = r[3];
                ldsm_x4(r, BL + bOff0 + kb);
                bl[0][0] = r[0]; bl[0][1] = r[1]; bl[1][0] = r[2]; bl[1][1] = r[3];
                ldsm_x4(r, BL + bOff1 + kb);
                bl[2][0] = r[0]; bl[2][1] = r[1]; bl[3][0] = r[2]; bl[3][1] = r[3];
            }
#pragma unroll
            for (int ni = 0; ni < 4; ni++)
                mma_bf16(acc[ni], ah, bh[ni]);
#pragma unroll
            for (int ni = 0; ni < 4; ni++)
                mma_bf16(acc[ni], ah, bl[ni]);
#pragma unroll
            for (int ni = 0; ni < 4; ni++)
                mma_bf16(acc[ni], al, bh[ni]);
        }

        __syncthreads();   // this chunk's B tiles dead; stage C over them

        int qrow = lane >> 2;
        int qcol = (lane & 3) * 2;
#pragma unroll
        for (int ni = 0; ni < 4; ni++) {
            int r0 = warpM + qrow;
            int c0 = warpN + ni * 8 + qcol;
            uint32_t addr = bufC + (uint32_t)(r0 * CPITCH + c0) * 4u;
            asm volatile("st.shared.v2.f32 [%0], {%1,%2};"
                         :: "r"(addr), "f"(acc[ni][0]), "f"(acc[ni][1]) : "memory");
            asm volatile("st.shared.v2.f32 [%0], {%1,%2};"
                         :: "r"(addr + 8u * CPITCH * 4u), "f"(acc[ni][2]), "f"(acc[ni][3]) : "memory");
        }
        __syncthreads();

        int cN = nb & 1;                   // 64-col half within the 128-col output block
        if (nb < 2) {
            // z chunk: partial scores + fp16 z store. Two rows per warp-iter (16 lanes each).
            float4 as4 = *reinterpret_cast<const float4*>(Wa + cN * 64 + l16 * 4);
            float4 ad4 = *reinterpret_cast<const float4*>(Wa + DIM + cN * 64 + l16 * 4);
#pragma unroll
            for (int it = 0; it < 4; it++) {
                int row = wid + (it * 2 + half) * 8;
                int grow = rowBase + row;
                bool ok = (grow < M);
                float4 v = make_float4(0.f, 0.f, 0.f, 0.f);
                if (ok)
                    asm volatile("ld.shared.v4.f32 {%0,%1,%2,%3}, [%4];"
                                 : "=f"(v.x), "=f"(v.y), "=f"(v.z), "=f"(v.w)
                                 : "r"(bufC + (uint32_t)(row * CPITCH + l16 * 4) * 4u));
                float ss = v.x * as4.x + v.y * as4.y + v.z * as4.z + v.w * as4.w;
                float sd = v.x * ad4.x + v.y * ad4.y + v.z * ad4.z + v.w * ad4.w;
#pragma unroll
                for (int o = 8; o > 0; o >>= 1) {      // reduce within 16-lane group
                    ss += __shfl_xor_sync(0xFFFFFFFFu, ss, o);
                    sd += __shfl_xor_sync(0xFFFFFFFFu, sd, o);
                }
                pss[it] += ss;
                psd[it] += sd;
                if (ok) {
                    __half2 h0 = __float22half2_rn(make_float2(v.x, v.y));
                    __half2 h1 = __float22half2_rn(make_float2(v.z, v.w));
                    uint2 u = make_uint2(*reinterpret_cast<uint32_t*>(&h0), *reinterpret_cast<uint32_t*>(&h1));
                    *reinterpret_cast<uint2*>(g_zh + (size_t)grow * DIM + cN * 64 + l16 * 4) = u;
                    if (nb == 1 && l16 == 0) {         // both 64-col partials accumulated
                        g_ssrc[grow] = pss[it];
                        g_sdst[grow] = psd[it];
                    }
                }
            }
        } else {
            // zi chunk: fp16 store
#pragma unroll
            for (int it = 0; it < 4; it++) {
                int row = wid + (it * 2 + half) * 8;
                int grow = rowBase + row;
                if (grow < M) {
                    float4 v;
                    asm volatile("ld.shared.v4.f32 {%0,%1,%2,%3}, [%4];"
                                 : "=f"(v.x), "=f"(v.y), "=f"(v.z), "=f"(v.w)
                                 : "r"(bufC + (uint32_t)(row * CPITCH + l16 * 4) * 4u));
                    __half2 h0 = __float22half2_rn(make_float2(v.x, v.y));
                    __half2 h1 = __float22half2_rn(make_float2(v.z, v.w));
                    uint2 u = make_uint2(*reinterpret_cast<uint32_t*>(&h0), *reinterpret_cast<uint32_t*>(&h1));
                    *reinterpret_cast<uint2*>(g_zih + (size_t)grow * DIM + cN * 64 + l16 * 4) = u;
                }
            }
        }
        __syncthreads();   // protect bufC (epilogue reads) from the next prefetch into it
    }
}

// ---------------- per-node softmax + fp16 gather-aggregate + relu epilogue ----------------
__global__ __launch_bounds__(256)
void aggregate_kernel(const float* __restrict__ edge_d,
                      const int* __restrict__ edge_src,
                      const float* __restrict__ W_V,
                      const float* __restrict__ Wa,
                      float* __restrict__ out_ext, int toBf16) {
    int warp = (blockIdx.x * blockDim.x + threadIdx.x) >> 5;
    int lane = threadIdx.x & 31;
    if (warp >= NNODES) return;

    float cva = W_V[0] * Wa[2 * DIM];
    float sdi = g_sdst[warp];

    int src = 0;
    float e = -1e30f;
    if (lane < DEG) {
        size_t ei = (size_t)warp * DEG + lane;
        src = edge_src[ei];
        e = g_ssrc[src] + sdi + edge_d[ei] * cva;
        e = (e >= 0.f) ? e : 0.01f * e;
    }
    float m = e;
#pragma unroll
    for (int o = 8; o > 0; o >>= 1) m = fmaxf(m, __shfl_xor_sync(0xFFFFFFFFu, m, o));
    float ex = (lane < DEG) ? __expf(e - m) : 0.f;
    float s = ex;
#pragma unroll
    for (int o = 8; o > 0; o >>= 1) s += __shfl_xor_sync(0xFFFFFFFFu, s, o);
    float alpha = ex / s;

    float4 acc = make_float4(0.f, 0.f, 0.f, 0.f);
#pragma unroll
    for (int k = 0; k < DEG; k++) {
        int   sk = __shfl_sync(0xFFFFFFFFu, src, k);
        float ak = __shfl_sync(0xFFFFFFFFu, alpha, k);
        uint2 u = *reinterpret_cast<const uint2*>(g_zh + (size_t)sk * DIM + lane * 4);
        __half2 h0 = *reinterpret_cast<__half2*>(&u.x);
        __half2 h1 = *reinterpret_cast<__half2*>(&u.y);
        float2 f0 = __half22float2(h0);
        float2 f1 = __half22float2(h1);
        acc.x += ak * f0.x;
        acc.y += ak * f0.y;
        acc.z += ak * f1.x;
        acc.w += ak * f1.y;
    }
    uint2 uz = *reinterpret_cast<const uint2*>(g_zih + (size_t)warp * DIM + lane * 4);
    __half2 zh0 = *reinterpret_cast<__half2*>(&uz.x);
    __half2 zh1 = *reinterpret_cast<__half2*>(&uz.y);
    float2 zi0 = __half22float2(zh0);
    float2 zi1 = __half22float2(zh1);
    float4 o4;
    o4.x = fmaxf(zi0.x + acc.x, 0.f);
    o4.y = fmaxf(zi0.y + acc.y, 0.f);
    o4.z = fmaxf(zi1.x + acc.z, 0.f);
    o4.w = fmaxf(zi1.y + acc.w, 0.f);

    if (toBf16) {
        __nv_bfloat16 hh[4], ll[4];
        split_bf16(o4.x, hh[0], ll[0]);
        split_bf16(o4.y, hh[1], ll[1]);
        split_bf16(o4.z, hh[2], ll[2]);
        split_bf16(o4.w, hh[3], ll[3]);
        size_t base = (size_t)warp * DIM + lane * 4;
        *reinterpret_cast<uint2*>(g_Ah + base) = *reinterpret_cast<uint2*>(hh);
        *reinterpret_cast<uint2*>(g_Al + base) = *reinterpret_cast<uint2*>(ll);
    } else {
        *reinterpret_cast<float4*>(out_ext + (size_t)warp * DIM + lane * 4) = o4;
    }
}

// ---------------- launch ----------------
extern "C" void kernel_launch(void* const* d_in, const int* in_sizes, int n_in,
                              void* d_out, int out_size) {
    const float* attr    = (const float*)d_in[0];
    const float* edge_d  = (const float*)d_in[1];
    const float* W_V1    = (const float*)d_in[2];
    const float* W_W1    = (const float*)d_in[3];
    const float* W_U1    = (const float*)d_in[4];
    const float* W_a1    = (const float*)d_in[5];
    const float* W_V2    = (const float*)d_in[6];
    const float* W_W2    = (const float*)d_in[7];
    const float* W_U2    = (const float*)d_in[8];
    const float* W_a2    = (const float*)d_in[9];
    const int*   edge_src = (const int*)d_in[10];
    float* out = (float*)d_out;

    static int smem_set = 0;
    if (!smem_set) {
        cudaFuncSetAttribute(mma_gemm_kernel, cudaFuncAttributeMaxDynamicSharedMemorySize, SMEM_DYN);
        smem_set = 1;
    }

    int gemm_grid = (NNODES + MROWS - 1) / MROWS;
    int warp_blocks = (NNODES * 32 + 255) / 256;

    prep_w_kernel<<<(2 * NC * DIM + 255) / 256, 256>>>(W_W1, W_U1, W_W2, W_U2);

    // ----- layer 1 -----
    mma_gemm_kernel<<<gemm_grid, 256, SMEM_DYN>>>(attr, W_a1, NNODES, 1, 0);
    aggregate_kernel<<<warp_blocks, 256>>>(edge_d, edge_src, W_V1, W_a1, nullptr, 1);

    // ----- layer 2 -----
    mma_gemm_kernel<<<gemm_grid, 256, SMEM_DYN>>>(nullptr, W_a2, NNODES, 0, 1);
    aggregate_kernel<<<warp_blocks, 256>>>(edge_d, edge_src, W_V2, W_a2, out, 0);
}

// round 16
// speedup vs baseline: 1.1916x; 1.1916x over previous
#include <cuda_runtime.h>
#include <cuda_bf16.h>
#include <cuda_fp16.h>
#include <cstdint>

#define NNODES 100000
#define DEG 16
#define DIM 128
#define NC 256
#define MROWS 64    // CTA row tile

// ---------------- scratch (no allocation allowed) ----------------
__device__ __half g_zh[(size_t)NNODES * DIM];                // z in fp16 (gather source)
__device__ __half g_zih[(size_t)NNODES * DIM];               // z_i in fp16
__device__ __half g_Ah[(size_t)NNODES * DIM];                // layer-2 GEMM input hi (fp16)
__device__ __half g_Al[(size_t)NNODES * DIM];                // layer-2 GEMM input lo (fp16)
__device__ __half g_Bh[2 * NC * DIM];                        // both layers' weights fp16 [256 x 128] K-contig
__device__ float g_ssrc[NNODES];
__device__ float g_sdst[NNODES];

__device__ __forceinline__ uint32_t smem_u32(const void* p) {
    uint32_t a;
    asm("{ .reg .u64 t; cvta.to.shared.u64 t, %1; cvt.u32.u64 %0, t; }" : "=r"(a) : "l"(p));
    return a;
}

__device__ __forceinline__ void split_half(float x, __half& h, __half& l) {
    h = __float2half_rn(x);
    l = __float2half_rn(x - __half2float(h));
}

// ---------------- weight prep (both layers, one launch; fp16 hi only) ----------------
__global__ void prep_w_kernel(const float* __restrict__ W_W1, const float* __restrict__ W_U1,
                              const float* __restrict__ W_W2, const float* __restrict__ W_U2) {
    int idx = blockIdx.x * blockDim.x + threadIdx.x;
    if (idx >= 2 * NC * DIM) return;
    int layer = idx / (NC * DIM);
    int li = idx - layer * (NC * DIM);
    const float* WW = layer ? W_W2 : W_W1;
    const float* WU = layer ? W_U2 : W_U1;
    float v = (li < DIM * DIM) ? WW[li] : WU[li - DIM * DIM];
    g_Bh[idx] = __float2half_rn(v);
}

// ---------------- mma.sync fp16 GEMM: [z | zi] = (Ah+Al) @ Bh^T, 2-pass fp16 split ----------------
// CTA = 64 rows, 256 threads, 8 warps 2M x 4N -> 32x32 warp tiles. 16 HMMA + 6 LDSM
// per warp per k-column. smem 69.6 KB/CTA. nb loop over the two 128-col N halves.
#define TPITCH 272
#define A_TILE_SM (MROWS * TPITCH)      // 17408 B
#define B_TILE_SM (128 * TPITCH)        // 34816 B (fp16 hi only)
#define CPITCH 132                      // fp32 staging pitch (floats); 64*132*4 = 33792 B
#define SMEM_DYN (2 * A_TILE_SM + B_TILE_SM)   // 69632 B

__device__ __forceinline__ void load_tile_f16(uint32_t sm_dst, const __half* __restrict__ gptr,
                                              int rowBase, int maxRows, int tid, int iters) {
    for (int it = 0; it < iters; it++) {
        int chunk = tid + it * 256;       // 16B chunks, 16 per row
        int row = chunk >> 4;
        int c8  = chunk & 15;
        uint4 v = make_uint4(0u, 0u, 0u, 0u);
        int grow = rowBase + row;
        if (grow < maxRows)
            v = *reinterpret_cast<const uint4*>(gptr + (size_t)grow * DIM + c8 * 8);
        asm volatile("st.shared.v4.b32 [%0], {%1,%2,%3,%4};"
                     :: "r"(sm_dst + row * TPITCH + c8 * 16),
                        "r"(v.x), "r"(v.y), "r"(v.z), "r"(v.w) : "memory");
    }
}

// fp32 source: split hi/lo while loading (layer-1 A = attr)
__device__ __forceinline__ void load_tile_fp32split(uint32_t sm_hi, uint32_t sm_lo,
                                                    const float* __restrict__ gptr,
                                                    int rowBase, int maxRows, int tid) {
#pragma unroll
    for (int it = 0; it < 4; it++) {
        int chunk = tid + it * 256;       // 1024 chunks (64 rows)
        int row = chunk >> 4;
        int c8  = chunk & 15;
        float f[8] = {0.f, 0.f, 0.f, 0.f, 0.f, 0.f, 0.f, 0.f};
        int grow = rowBase + row;
        if (grow < maxRows) {
            const float4* p = reinterpret_cast<const float4*>(gptr + (size_t)grow * DIM + c8 * 8);
            float4 v0 = p[0], v1 = p[1];
            f[0] = v0.x; f[1] = v0.y; f[2] = v0.z; f[3] = v0.w;
            f[4] = v1.x; f[5] = v1.y; f[6] = v1.z; f[7] = v1.w;
        }
        __half hh[8], ll[8];
#pragma unroll
        for (int j = 0; j < 8; j++) split_half(f[j], hh[j], ll[j]);
        uint4 vh = *reinterpret_cast<uint4*>(hh);
        uint4 vl = *reinterpret_cast<uint4*>(ll);
        uint32_t off = (uint32_t)(row * TPITCH + c8 * 16);
        asm volatile("st.shared.v4.b32 [%0], {%1,%2,%3,%4};"
                     :: "r"(sm_hi + off), "r"(vh.x), "r"(vh.y), "r"(vh.z), "r"(vh.w) : "memory");
        asm volatile("st.shared.v4.b32 [%0], {%1,%2,%3,%4};"
                     :: "r"(sm_lo + off), "r"(vl.x), "r"(vl.y), "r"(vl.z), "r"(vl.w) : "memory");
    }
}

__device__ __forceinline__ void ldsm_x4(uint32_t* r, uint32_t addr) {
    asm volatile("ldmatrix.sync.aligned.m8n8.x4.shared.b16 {%0,%1,%2,%3}, [%4];"
                 : "=r"(r[0]), "=r"(r[1]), "=r"(r[2]), "=r"(r[3]) : "r"(addr));
}
__device__ __forceinline__ void mma_f16(float* d, const uint32_t* a, const uint32_t* b) {
    asm volatile("mma.sync.aligned.m16n8k16.row.col.f32.f16.f16.f32 "
                 "{%0,%1,%2,%3}, {%4,%5,%6,%7}, {%8,%9}, {%0,%1,%2,%3};"
                 : "+f"(d[0]), "+f"(d[1]), "+f"(d[2]), "+f"(d[3])
                 : "r"(a[0]), "r"(a[1]), "r"(a[2]), "r"(a[3]), "r"(b[0]), "r"(b[1]));
}

__global__ __launch_bounds__(256, 2)
void mma_gemm_kernel(const float* __restrict__ attr, const float* __restrict__ Wa,
                     int M, int srcFp32, int layer) {
    extern __shared__ char dynsmem[];
    uint32_t s0 = smem_u32(dynsmem);
    const uint32_t SM_AH = s0;
    const uint32_t SM_AL = s0 + A_TILE_SM;
    const uint32_t SM_BH = s0 + 2 * A_TILE_SM;
    const uint32_t SM_C  = SM_BH;              // C staging overlays BH (33792 <= 34816)

    int tid  = threadIdx.x;
    int wid  = tid >> 5;
    int lane = tid & 31;
    int warpM = (wid & 1) * 32;                // 2 warps along M (32 rows each)
    int warpN = (wid >> 1) * 32;               // 4 warps along N (32 cols each)
    int rowBase = blockIdx.x * MROWS;

    if (srcFp32)
        load_tile_fp32split(SM_AH, SM_AL, attr, rowBase, M, tid);
    else {
        load_tile_f16(SM_AH, g_Ah, rowBase, M, tid, 4);
        load_tile_f16(SM_AL, g_Al, rowBase, M, tid, 4);
    }

    int aRow = (lane & 15);
    int aK   = (lane >> 4) << 3;
    int bRow = (lane & 7) + ((lane >> 4) << 3);
    int bK   = ((lane >> 3) & 1) << 3;

    uint32_t aBase0 = (warpM +  0 + aRow) * TPITCH + aK * 2;
    uint32_t aBase1 = (warpM + 16 + aRow) * TPITCH + aK * 2;
    uint32_t bBase0 = (warpN +  0 + bRow) * TPITCH + bK * 2;
    uint32_t bBase1 = (warpN + 16 + bRow) * TPITCH + bK * 2;

    int c4 = lane;                       // float4 column group in the 128-col half
    float4 as4 = *reinterpret_cast<const float4*>(Wa + c4 * 4);
    float4 ad4 = *reinterpret_cast<const float4*>(Wa + DIM + c4 * 4);

#pragma unroll
    for (int nb = 0; nb < 2; nb++) {
        // previous iteration's epilogue reads from the B region — barrier before overwrite
        __syncthreads();
        const __half* Bh = g_Bh + ((size_t)layer * NC + nb * 128) * DIM;
        load_tile_f16(SM_BH, Bh, 0, 1 << 30, tid, 8);
        __syncthreads();

        float acc[2][4][4];
#pragma unroll
        for (int mi = 0; mi < 2; mi++)
#pragma unroll
            for (int ni = 0; ni < 4; ni++)
#pragma unroll
                for (int j = 0; j < 4; j++) acc[mi][ni][j] = 0.f;

#pragma unroll
        for (int ks = 0; ks < 8; ks++) {
            uint32_t kb = (uint32_t)ks * 32u;  // 16 cols * 2B
            uint32_t ah[2][4], al[2][4];
            ldsm_x4(ah[0], SM_AH + aBase0 + kb);
            ldsm_x4(ah[1], SM_AH + aBase1 + kb);
            ldsm_x4(al[0], SM_AL + aBase0 + kb);
            ldsm_x4(al[1], SM_AL + aBase1 + kb);
            uint32_t bh[4][2];
            {
                uint32_t r[4];
                ldsm_x4(r, SM_BH + bBase0 + kb);
                bh[0][0] = r[0]; bh[0][1] = r[1]; bh[1][0] = r[2]; bh[1][1] = r[3];
                ldsm_x4(r, SM_BH + bBase1 + kb);
                bh[2][0] = r[0]; bh[2][1] = r[1]; bh[3][0] = r[2]; bh[3][1] = r[3];
            }
#pragma unroll
            for (int mi = 0; mi < 2; mi++)
#pragma unroll
                for (int ni = 0; ni < 4; ni++)
                    mma_f16(acc[mi][ni], ah[mi], bh[ni]);
#pragma unroll
            for (int mi = 0; mi < 2; mi++)
#pragma unroll
                for (int ni = 0; ni < 4; ni++)
                    mma_f16(acc[mi][ni], al[mi], bh[ni]);
        }

        __syncthreads();   // B tile dead; stage C over it

        int qrow = lane >> 2;
        int qcol = (lane & 3) * 2;
#pragma unroll
        for (int mi = 0; mi < 2; mi++)
#pragma unroll
            for (int ni = 0; ni < 4; ni++) {
                int r0 = warpM + mi * 16 + qrow;
                int c0 = warpN + ni * 8 + qcol;
                uint32_t addr = SM_C + (uint32_t)(r0 * CPITCH + c0) * 4u;
                asm volatile("st.shared.v2.f32 [%0], {%1,%2};"
                             :: "r"(addr), "f"(acc[mi][ni][0]), "f"(acc[mi][ni][1]) : "memory");
                asm volatile("st.shared.v2.f32 [%0], {%1,%2};"
                             :: "r"(addr + 8u * CPITCH * 4u), "f"(acc[mi][ni][2]), "f"(acc[mi][ni][3]) : "memory");
            }
        __syncthreads();

        if (nb == 0) {
            // z half: fused attention scores + fp16 z store. One warp per row.
#pragma unroll
            for (int it = 0; it < 8; it++) {
                int row = wid + it * 8;
                int grow = rowBase + row;
                bool ok = (grow < M);
                float4 v = make_float4(0.f, 0.f, 0.f, 0.f);
                if (ok)
                    asm volatile("ld.shared.v4.f32 {%0,%1,%2,%3}, [%4];"
                                 : "=f"(v.x), "=f"(v.y), "=f"(v.z), "=f"(v.w)
                                 : "r"(SM_C + (uint32_t)(row * CPITCH + c4 * 4) * 4u));
                float ss = v.x * as4.x + v.y * as4.y + v.z * as4.z + v.w * as4.w;
                float sd = v.x * ad4.x + v.y * ad4.y + v.z * ad4.z + v.w * ad4.w;
#pragma unroll
                for (int o = 16; o > 0; o >>= 1) {
                    ss += __shfl_xor_sync(0xFFFFFFFFu, ss, o);
                    sd += __shfl_xor_sync(0xFFFFFFFFu, sd, o);
                }
                if (ok) {
                    if (lane == 0) { g_ssrc[grow] = ss; g_sdst[grow] = sd; }
                    __half2 h0 = __float22half2_rn(make_float2(v.x, v.y));
                    __half2 h1 = __float22half2_rn(make_float2(v.z, v.w));
                    uint2 u = make_uint2(*reinterpret_cast<uint32_t*>(&h0), *reinterpret_cast<uint32_t*>(&h1));
                    *reinterpret_cast<uint2*>(g_zh + (size_t)grow * DIM + c4 * 4) = u;
                }
            }
        } else {
            // zi half: fp16 store
#pragma unroll
            for (int it = 0; it < 8; it++) {
                int row = wid + it * 8;
                int grow = rowBase + row;
                if (grow < M) {
                    float4 v;
                    asm volatile("ld.shared.v4.f32 {%0,%1,%2,%3}, [%4];"
                                 : "=f"(v.x), "=f"(v.y), "=f"(v.z), "=f"(v.w)
                                 : "r"(SM_C + (uint32_t)(row * CPITCH + c4 * 4) * 4u));
                    __half2 h0 = __float22half2_rn(make_float2(v.x, v.y));
                    __half2 h1 = __float22half2_rn(make_float2(v.z, v.w));
                    uint2 u = make_uint2(*reinterpret_cast<uint32_t*>(&h0), *reinterpret_cast<uint32_t*>(&h1));
                    *reinterpret_cast<uint2*>(g_zih + (size_t)grow * DIM + c4 * 4) = u;
                }
            }
        }
    }
}

// ---------------- per-node softmax + fp16 gather-aggregate + relu epilogue ----------------
__global__ __launch_bounds__(256)
void aggregate_kernel(const float* __restrict__ edge_d,
                      const int* __restrict__ edge_src,
                      const float* __restrict__ W_V,
                      const float* __restrict__ Wa,
                      float* __restrict__ out_ext, int toHalf) {
    int warp = (blockIdx.x * blockDim.x + threadIdx.x) >> 5;
    int lane = threadIdx.x & 31;
    if (warp >= NNODES) return;

    float cva = W_V[0] * Wa[2 * DIM];
    float sdi = g_sdst[warp];

    int src = 0;
    float e = -1e30f;
    if (lane < DEG) {
        size_t ei = (size_t)warp * DEG + lane;
        src = edge_src[ei];
        e = g_ssrc[src] + sdi + edge_d[ei] * cva;
        e = (e >= 0.f) ? e : 0.01f * e;
    }
    float m = e;
#pragma unroll
    for (int o = 8; o > 0; o >>= 1) m = fmaxf(m, __shfl_xor_sync(0xFFFFFFFFu, m, o));
    float ex = (lane < DEG) ? __expf(e - m) : 0.f;
    float s = ex;
#pragma unroll
    for (int o = 8; o > 0; o >>= 1) s += __shfl_xor_sync(0xFFFFFFFFu, s, o);
    float alpha = ex / s;

    float4 acc = make_float4(0.f, 0.f, 0.f, 0.f);
#pragma unroll
    for (int k = 0; k < DEG; k++) {
        int   sk = __shfl_sync(0xFFFFFFFFu, src, k);
        float ak = __shfl_sync(0xFFFFFFFFu, alpha, k);
        uint2 u = *reinterpret_cast<const uint2*>(g_zh + (size_t)sk * DIM + lane * 4);
        __half2 h0 = *reinterpret_cast<__half2*>(&u.x);
        __half2 h1 = *reinterpret_cast<__half2*>(&u.y);
        float2 f0 = __half22float2(h0);
        float2 f1 = __half22float2(h1);
        acc.x += ak * f0.x;
        acc.y += ak * f0.y;
        acc.z += ak * f1.x;
        acc.w += ak * f1.y;
    }
    uint2 uz = *reinterpret_cast<const uint2*>(g_zih + (size_t)warp * DIM + lane * 4);
    __half2 zh0 = *reinterpret_cast<__half2*>(&uz.x);
    __half2 zh1 = *reinterpret_cast<__half2*>(&uz.y);
    float2 zi0 = __half22float2(zh0);
    float2 zi1 = __half22float2(zh1);
    float4 o4;
    o4.x = fmaxf(zi0.x + acc.x, 0.f);
    o4.y = fmaxf(zi0.y + acc.y, 0.f);
    o4.z = fmaxf(zi1.x + acc.z, 0.f);
    o4.w = fmaxf(zi1.y + acc.w, 0.f);

    if (toHalf) {
        __half hh[4], ll[4];
        split_half(o4.x, hh[0], ll[0]);
        split_half(o4.y, hh[1], ll[1]);
        split_half(o4.z, hh[2], ll[2]);
        split_half(o4.w, hh[3], ll[3]);
        size_t base = (size_t)warp * DIM + lane * 4;
        *reinterpret_cast<uint2*>(g_Ah + base) = *reinterpret_cast<uint2*>(hh);
        *reinterpret_cast<uint2*>(g_Al + base) = *reinterpret_cast<uint2*>(ll);
    } else {
        *reinterpret_cast<float4*>(out_ext + (size_t)warp * DIM + lane * 4) = o4;
    }
}

// ---------------- launch ----------------
extern "C" void kernel_launch(void* const* d_in, const int* in_sizes, int n_in,
                              void* d_out, int out_size) {
    const float* attr    = (const float*)d_in[0];
    const float* edge_d  = (const float*)d_in[1];
    const float* W_V1    = (const float*)d_in[2];
    const float* W_W1    = (const float*)d_in[3];
    const float* W_U1    = (const float*)d_in[4];
    const float* W_a1    = (const float*)d_in[5];
    const float* W_V2    = (const float*)d_in[6];
    const float* W_W2    = (const float*)d_in[7];
    const float* W_U2    = (const float*)d_in[8];
    const float* W_a2    = (const float*)d_in[9];
    const int*   edge_src = (const int*)d_in[10];
    float* out = (float*)d_out;

    static int smem_set = 0;
    if (!smem_set) {
        cudaFuncSetAttribute(mma_gemm_kernel, cudaFuncAttributeMaxDynamicSharedMemorySize, SMEM_DYN);
        smem_set = 1;
    }

    int gemm_grid = (NNODES + MROWS - 1) / MROWS;
    int warp_blocks = (NNODES * 32 + 255) / 256;

    prep_w_kernel<<<(2 * NC * DIM + 255) / 256, 256>>>(W_W1, W_U1, W_W2, W_U2);

    // ----- layer 1 -----
    mma_gemm_kernel<<<gemm_grid, 256, SMEM_DYN>>>(attr, W_a1, NNODES, 1, 0);
    aggregate_kernel<<<warp_blocks, 256>>>(edge_d, edge_src, W_V1, W_a1, nullptr, 1);

    // ----- layer 2 -----
    mma_gemm_kernel<<<gemm_grid, 256, SMEM_DYN>>>(nullptr, W_a2, NNODES, 0, 1);
    aggregate_kernel<<<warp_blocks, 256>>>(edge_d, edge_src, W_V2, W_a2, out, 0);
}